// round 3
// baseline (speedup 1.0000x reference)
#include <cuda_runtime.h>
#include <cstdint>

// ---------------- problem constants ----------------
#define DMODEL 2048
#define MTOT   16384          // B*S
#define NQKV   6144           // 3*DMODEL

// ---------------- GEMM tiling ----------------------
#define BM 128
#define BN 128
#define BK 32
#define NST 4
#define KT (DMODEL / BK)      // 64
#define STAGE_A (BM * 128)    // 16 KB (BK=32 fp32 = 128 B/row)
#define STAGE_B (BN * 128)    // 16 KB
#define STAGE_BYTES (STAGE_A + STAGE_B)
#define SMEM_GEMM (1024 + NST * STAGE_BYTES)   // 132096 B

// ---------------- device scratch --------------------
__device__ float g_Xr   [(size_t)MTOT * DMODEL];
__device__ float g_WTqkv[(size_t)NQKV * DMODEL];
__device__ float g_WT1  [(size_t)DMODEL * DMODEL];
__device__ float g_WT2  [(size_t)DMODEL * DMODEL];
__device__ float g_bcat [NQKV];
__device__ float g_QKV  [(size_t)MTOT * NQKV];
__device__ float g_Att  [(size_t)MTOT * DMODEL];
__device__ float g_X1   [(size_t)MTOT * DMODEL];
__device__ float g_Hbuf [(size_t)MTOT * DMODEL];
__device__ float g_Y2   [(size_t)MTOT * DMODEL];

// ---------------- helpers ---------------------------
__device__ __forceinline__ uint32_t smem_u32(const void* p) {
    uint32_t a;
    asm("{ .reg .u64 t; cvta.to.shared.u64 t, %1; cvt.u32.u64 %0, t; }" : "=r"(a) : "l"(p));
    return a;
}
__device__ __forceinline__ float rna_tf32(float x) {
    uint32_t u;
    asm("cvt.rna.tf32.f32 %0, %1;" : "=r"(u) : "f"(x));
    return __uint_as_float(u);
}
__device__ __forceinline__ void cp_async16(uint32_t saddr, const void* g) {
    asm volatile("cp.async.cg.shared.global [%0], [%1], 16;" :: "r"(saddr), "l"(g) : "memory");
}
__device__ __forceinline__ float lds_f32(uint32_t a) {
    float v;
    asm volatile("ld.shared.f32 %0, [%1];" : "=f"(v) : "r"(a));
    return v;
}
// swizzled byte offset of element (row, col) in a [rows x 32] fp32 tile, 128B rows
__device__ __forceinline__ uint32_t swaddr(int row, int col) {
    uint32_t off = (uint32_t)(row * 128 + col * 4);
    return off ^ (((uint32_t)row & 7u) << 4);
}
// D += A*B for m16n8k8 tf32 (operands pre-rounded to tf32-representable fp32)
__device__ __forceinline__ void mma8(float* d, const float* a, const float* b) {
    asm volatile(
        "mma.sync.aligned.m16n8k8.row.col.f32.tf32.tf32.f32 "
        "{%0,%1,%2,%3}, {%4,%5,%6,%7}, {%8,%9}, {%0,%1,%2,%3};"
        : "+f"(d[0]), "+f"(d[1]), "+f"(d[2]), "+f"(d[3])
        : "r"(__float_as_uint(a[0])), "r"(__float_as_uint(a[1])),
          "r"(__float_as_uint(a[2])), "r"(__float_as_uint(a[3])),
          "r"(__float_as_uint(b[0])), "r"(__float_as_uint(b[1])));
}

// ---------------- GEMM: C[m][n] = sum_k A[m][k]*B[n][k] + bias[n] -----------
__device__ __forceinline__ void load_stage(uint32_t sb, const float* __restrict__ gA,
                                           const float* __restrict__ gB, int s) {
    int tid = threadIdx.x;
    uint32_t base = sb + 1024 + (uint32_t)(s % NST) * STAGE_BYTES;
    const float* ga = gA + (size_t)s * BK;
    const float* gb = gB + (size_t)s * BK;
#pragma unroll
    for (int i = 0; i < 4; i++) {
        int c = tid + i * 256;
        int row = c >> 3, c16 = c & 7;             // 8 x 16B segments per 128B row
        uint32_t off = (uint32_t)(row * 128 + c16 * 16);
        uint32_t sw = off ^ ((off >> 3) & 0x70);
        cp_async16(base + sw, ga + (size_t)row * DMODEL + c16 * 4);
    }
#pragma unroll
    for (int i = 0; i < 4; i++) {
        int c = tid + i * 256;
        int row = c >> 3, c16 = c & 7;
        uint32_t off = (uint32_t)(row * 128 + c16 * 16);
        uint32_t sw = off ^ ((off >> 3) & 0x70);
        cp_async16(base + STAGE_A + sw, gb + (size_t)row * DMODEL + c16 * 4);
    }
}

__global__ void __launch_bounds__(256, 1) gemm_tf32(
    const float* __restrict__ A, const float* __restrict__ B,
    const float* __restrict__ bias, float* __restrict__ C,
    int Ntot, int act)
{
    extern __shared__ __align__(1024) char smem[];
    uint32_t sb = smem_u32(smem);
    const int NT = Ntot / BN;
    int tileM = blockIdx.x / NT;
    int tileN = blockIdx.x % NT;                   // n fastest -> B stays L2-resident
    size_t m0 = (size_t)tileM * BM;
    size_t n0 = (size_t)tileN * BN;
    int tid = threadIdx.x, wid = tid >> 5, lane = tid & 31;
    int wm = wid & 1, wn = wid >> 1;               // 2(M) x 4(N) warp grid, 64x32 warp tile
    int lr = lane >> 2;                            // 0..7
    int lc = lane & 3;                             // 0..3

    const float* gA = A + m0 * DMODEL;
    const float* gB = B + n0 * DMODEL;

    float acc[4][4][4];
#pragma unroll
    for (int i = 0; i < 4; i++)
#pragma unroll
        for (int j = 0; j < 4; j++)
#pragma unroll
            for (int r = 0; r < 4; r++) acc[i][j][r] = 0.f;

    for (int s = 0; s < NST - 1; s++) {
        load_stage(sb, gA, gB, s);
        asm volatile("cp.async.commit_group;" ::: "memory");
    }

    for (int kt = 0; kt < KT; kt++) {
        asm volatile("cp.async.wait_group %0;" :: "n"(NST - 2) : "memory");
        __syncthreads();

        uint32_t sA = sb + 1024 + (uint32_t)(kt % NST) * STAGE_BYTES;
        uint32_t sB = sA + STAGE_A;
#pragma unroll
        for (int ks = 0; ks < 4; ks++) {
            const int k0 = ks * 8;
            float a[4][4];
#pragma unroll
            for (int mf = 0; mf < 4; mf++) {
                int r0 = wm * 64 + mf * 16 + lr;
                a[mf][0] = lds_f32(sA + swaddr(r0,     k0 + lc));
                a[mf][1] = lds_f32(sA + swaddr(r0 + 8, k0 + lc));
                a[mf][2] = lds_f32(sA + swaddr(r0,     k0 + lc + 4));
                a[mf][3] = lds_f32(sA + swaddr(r0 + 8, k0 + lc + 4));
            }
            float b[4][2];
#pragma unroll
            for (int nf = 0; nf < 4; nf++) {
                int n = wn * 32 + nf * 8 + lr;
                b[nf][0] = lds_f32(sB + swaddr(n, k0 + lc));
                b[nf][1] = lds_f32(sB + swaddr(n, k0 + lc + 4));
            }
#pragma unroll
            for (int mf = 0; mf < 4; mf++)
#pragma unroll
                for (int nf = 0; nf < 4; nf++)
                    mma8(acc[mf][nf], a[mf], b[nf]);
        }
        __syncthreads();
        if (kt + NST - 1 < KT) load_stage(sb, gA, gB, kt + NST - 1);
        asm volatile("cp.async.commit_group;" ::: "memory");  // empty group in tail keeps counts uniform
    }

    // ---- epilogue: bias (+ exact GELU + tf32 round), vectorized stores ----
#pragma unroll
    for (int mf = 0; mf < 4; mf++) {
        size_t row0 = m0 + (size_t)(wm * 64 + mf * 16 + lr);
#pragma unroll
        for (int nf = 0; nf < 4; nf++) {
            size_t col = n0 + (size_t)(wn * 32 + nf * 8 + 2 * lc);
            float b0 = __ldg(bias + col), b1 = __ldg(bias + col + 1);
            float v[4] = { acc[mf][nf][0] + b0, acc[mf][nf][1] + b1,
                           acc[mf][nf][2] + b0, acc[mf][nf][3] + b1 };
            if (act) {
#pragma unroll
                for (int r = 0; r < 4; r++) {
                    float x = v[r];
                    x = 0.5f * x * (1.0f + erff(x * 0.70710678118654752f));
                    v[r] = rna_tf32(x);
                }
            }
            *(float2*)(C + row0 * (size_t)Ntot + col)       = make_float2(v[0], v[1]);
            *(float2*)(C + (row0 + 8) * (size_t)Ntot + col) = make_float2(v[2], v[3]);
        }
    }
}

// ---------------- attention (per-token head x head softmax) ----------------
__global__ void __launch_bounds__(128) attn_kernel(const float* __restrict__ QKV,
                                                   float* __restrict__ Y)
{
    __shared__ float sq[2048], sk[2048], sv[2048];
    __shared__ float att[16][17];
    int m = blockIdx.x;
    int tid = threadIdx.x;
    const float4* src = (const float4*)(QKV + (size_t)m * NQKV);
#pragma unroll
    for (int i = 0; i < 4; i++) ((float4*)sq)[tid + i * 128] = src[tid + i * 128];
#pragma unroll
    for (int i = 0; i < 4; i++) ((float4*)sk)[tid + i * 128] = src[512 + tid + i * 128];
#pragma unroll
    for (int i = 0; i < 4; i++) ((float4*)sv)[tid + i * 128] = src[1024 + tid + i * 128];
    __syncthreads();

    int lane = tid & 31;
#pragma unroll
    for (int pp = 0; pp < 2; pp++) {
        int p = tid + pp * 128;
        int h = p >> 4, t = p & 15;
        float s = 0.f;
#pragma unroll 8
        for (int i = 0; i < 128; i++) {
            int idx = (lane + i) & 127;          // bank-conflict-free rotation
            s += sq[h * 128 + idx] * sk[t * 128 + idx];
        }
        att[h][t] = s * 0.08838834764831843f;    // 1/sqrt(128)
    }
    __syncthreads();

    if (tid < 16) {
        float mx = -1e30f;
#pragma unroll
        for (int t = 0; t < 16; t++) mx = fmaxf(mx, att[tid][t]);
        float s = 0.f;
#pragma unroll
        for (int t = 0; t < 16; t++) { float e = expf(att[tid][t] - mx); att[tid][t] = e; s += e; }
        float inv = 1.f / s;
#pragma unroll
        for (int t = 0; t < 16; t++) att[tid][t] *= inv;
    }
    __syncthreads();

    int d = tid;  // 0..127
    float* yrow = Y + (size_t)m * DMODEL;
#pragma unroll
    for (int h = 0; h < 16; h++) {
        float s = 0.f;
#pragma unroll
        for (int t = 0; t < 16; t++) s += att[h][t] * sv[t * 128 + d];
        yrow[h * 128 + d] = s;
    }
}

// ---------------- layer norm (a [+ b] -> LN -> optional tf32 round) --------
__global__ void __launch_bounds__(256) ln_kernel(
    const float* __restrict__ a, const float* __restrict__ b,
    const float* __restrict__ g, const float* __restrict__ beta,
    float* __restrict__ out, int doRound)
{
    __shared__ float red[16];
    int m = blockIdx.x, tid = threadIdx.x;
    int wid = tid >> 5, lane = tid & 31;
    const float4* pa = (const float4*)(a + (size_t)m * DMODEL);
    float4 v0 = pa[tid], v1 = pa[tid + 256];
    if (b) {
        const float4* pb = (const float4*)(b + (size_t)m * DMODEL);
        float4 w0 = pb[tid], w1 = pb[tid + 256];
        v0.x += w0.x; v0.y += w0.y; v0.z += w0.z; v0.w += w0.w;
        v1.x += w1.x; v1.y += w1.y; v1.z += w1.z; v1.w += w1.w;
    }
    float x[8] = {v0.x, v0.y, v0.z, v0.w, v1.x, v1.y, v1.z, v1.w};
    float s = 0.f, s2 = 0.f;
#pragma unroll
    for (int i = 0; i < 8; i++) { s += x[i]; s2 += x[i] * x[i]; }
#pragma unroll
    for (int o = 16; o; o >>= 1) {
        s += __shfl_xor_sync(0xffffffffu, s, o);
        s2 += __shfl_xor_sync(0xffffffffu, s2, o);
    }
    if (lane == 0) { red[wid] = s; red[8 + wid] = s2; }
    __syncthreads();
    if (tid == 0) {
        float ts = 0.f, t2 = 0.f;
#pragma unroll
        for (int i = 0; i < 8; i++) { ts += red[i]; t2 += red[8 + i]; }
        float mean = ts * (1.f / DMODEL);
        float var = t2 * (1.f / DMODEL) - mean * mean;
        red[0] = mean;
        red[1] = rsqrtf(var + 1e-5f);
    }
    __syncthreads();
    float mean = red[0], inv = red[1];

    const float4* pg = (const float4*)g;
    const float4* pbt = (const float4*)beta;
    float4* po = (float4*)(out + (size_t)m * DMODEL);
#pragma unroll
    for (int half = 0; half < 2; half++) {
        int vi = tid + half * 256;
        float4 gg = pg[vi], bb = pbt[vi];
        float4 y;
        y.x = (x[half * 4 + 0] - mean) * inv * gg.x + bb.x;
        y.y = (x[half * 4 + 1] - mean) * inv * gg.y + bb.y;
        y.z = (x[half * 4 + 2] - mean) * inv * gg.z + bb.z;
        y.w = (x[half * 4 + 3] - mean) * inv * gg.w + bb.w;
        if (doRound) {
            y.x = rna_tf32(y.x); y.y = rna_tf32(y.y);
            y.z = rna_tf32(y.z); y.w = rna_tf32(y.w);
        }
        po[vi] = y;
    }
}

// ---------------- prep kernels ----------------------
__global__ void round_tf32_kernel(const float* __restrict__ in, float* __restrict__ out, int nvec) {
    int i = blockIdx.x * blockDim.x + threadIdx.x;
    if (i < nvec) {
        float4 v = ((const float4*)in)[i];
        v.x = rna_tf32(v.x); v.y = rna_tf32(v.y);
        v.z = rna_tf32(v.z); v.w = rna_tf32(v.w);
        ((float4*)out)[i] = v;
    }
}

// out[n][k] = rna(in[k][n]), both 2048x2048 row-major
__global__ void transpose_rna_kernel(const float* __restrict__ in, float* __restrict__ out) {
    __shared__ float t[32][33];
    int bx = blockIdx.x * 32, by = blockIdx.y * 32;
    int tx = threadIdx.x, ty = threadIdx.y;
    for (int j = ty; j < 32; j += 8)
        t[j][tx] = in[(size_t)(by + j) * DMODEL + bx + tx];
    __syncthreads();
    for (int j = ty; j < 32; j += 8)
        out[(size_t)(bx + j) * DMODEL + by + tx] = rna_tf32(t[tx][j]);
}

__global__ void concat_bias_kernel(const float* __restrict__ bq, const float* __restrict__ bk,
                                   const float* __restrict__ bv, float* __restrict__ o) {
    int i = blockIdx.x * blockDim.x + threadIdx.x;
    if (i < NQKV)
        o[i] = (i < DMODEL) ? bq[i] : (i < 2 * DMODEL ? bk[i - DMODEL] : bv[i - 2 * DMODEL]);
}

// ---------------- launch -----------------------------
extern "C" void kernel_launch(void* const* d_in, const int* in_sizes, int n_in,
                              void* d_out, int out_size)
{
    const float* X    = (const float*)d_in[0];
    const float* Wq   = (const float*)d_in[1];
    const float* bq   = (const float*)d_in[2];
    const float* Wk   = (const float*)d_in[3];
    const float* bk   = (const float*)d_in[4];
    const float* Wv   = (const float*)d_in[5];
    const float* bv   = (const float*)d_in[6];
    const float* g1   = (const float*)d_in[7];
    const float* bt1  = (const float*)d_in[8];
    const float* W1   = (const float*)d_in[9];
    const float* b1   = (const float*)d_in[10];
    const float* W2   = (const float*)d_in[11];
    const float* b2   = (const float*)d_in[12];
    const float* g2   = (const float*)d_in[13];
    const float* bt2  = (const float*)d_in[14];
    float* out = (float*)d_out;

    float *pXr, *pWTqkv, *pWT1, *pWT2, *pbcat, *pQKV, *pAtt, *pX1, *pH, *pY2;
    cudaGetSymbolAddress((void**)&pXr,    g_Xr);
    cudaGetSymbolAddress((void**)&pWTqkv, g_WTqkv);
    cudaGetSymbolAddress((void**)&pWT1,   g_WT1);
    cudaGetSymbolAddress((void**)&pWT2,   g_WT2);
    cudaGetSymbolAddress((void**)&pbcat,  g_bcat);
    cudaGetSymbolAddress((void**)&pQKV,   g_QKV);
    cudaGetSymbolAddress((void**)&pAtt,   g_Att);
    cudaGetSymbolAddress((void**)&pX1,    g_X1);
    cudaGetSymbolAddress((void**)&pH,     g_Hbuf);
    cudaGetSymbolAddress((void**)&pY2,    g_Y2);

    cudaFuncSetAttribute(gemm_tf32, cudaFuncAttributeMaxDynamicSharedMemorySize, SMEM_GEMM);

    // prep: round activations, transpose+round weights, concat qkv bias
    round_tf32_kernel<<<(MTOT * DMODEL / 4 + 255) / 256, 256>>>(X, pXr, MTOT * DMODEL / 4);
    dim3 tb(32, 8), tg(DMODEL / 32, DMODEL / 32);
    transpose_rna_kernel<<<tg, tb>>>(Wq, pWTqkv);
    transpose_rna_kernel<<<tg, tb>>>(Wk, pWTqkv + (size_t)DMODEL * DMODEL);
    transpose_rna_kernel<<<tg, tb>>>(Wv, pWTqkv + (size_t)2 * DMODEL * DMODEL);
    transpose_rna_kernel<<<tg, tb>>>(W1, pWT1);
    transpose_rna_kernel<<<tg, tb>>>(W2, pWT2);
    concat_bias_kernel<<<(NQKV + 255) / 256, 256>>>(bq, bk, bv, pbcat);

    // fused QKV projection: [16384 x 2048] @ [2048 x 6144]
    gemm_tf32<<<(MTOT / BM) * (NQKV / BN), 256, SMEM_GEMM>>>(pXr, pWTqkv, pbcat, pQKV, NQKV, 0);
    // per-token head-softmax attention
    attn_kernel<<<MTOT, 128>>>(pQKV, pAtt);
    // residual + LN1 (tf32-rounded: feeds next GEMM)
    ln_kernel<<<MTOT, 256>>>(X, pAtt, g1, bt1, pX1, 1);
    // FFN1 with exact GELU (output tf32-rounded as next A)
    gemm_tf32<<<(MTOT / BM) * (DMODEL / BN), 256, SMEM_GEMM>>>(pX1, pWT1, b1, pH, DMODEL, 1);
    // FFN2
    gemm_tf32<<<(MTOT / BM) * (DMODEL / BN), 256, SMEM_GEMM>>>(pH, pWT2, b2, pY2, DMODEL, 0);
    // residual + LN2 -> output
    ln_kernel<<<MTOT, 256>>>(pX1, pY2, g2, bt2, out, 0);
}

// round 4
// speedup vs baseline: 1.0123x; 1.0123x over previous
#include <cuda_runtime.h>
#include <cstdint>

// ---------------- problem constants ----------------
#define DMODEL 2048
#define MTOT   16384          // B*S
#define NQKV   6144           // 3*DMODEL
#define NVECX  (MTOT * DMODEL / 4)

// ---------------- GEMM tiling ----------------------
#define BM 128
#define BN 128
#define BK 64
#define NST 3
#define KT (DMODEL / BK)      // 32
#define STAGE_A (BM * 256)    // 32 KB (two 128B-row sub-tiles)
#define STAGE_B (BN * 256)    // 32 KB
#define STAGE_BYTES (STAGE_A + STAGE_B)              // 64 KB
#define SMEM_GEMM (1024 + NST * STAGE_BYTES)         // 197632 B

// ---------------- device scratch --------------------
__device__ float g_Xr   [(size_t)MTOT * DMODEL];
__device__ float g_WTqkv[(size_t)NQKV * DMODEL];
__device__ float g_WT1  [(size_t)DMODEL * DMODEL];
__device__ float g_WT2  [(size_t)DMODEL * DMODEL];
__device__ float g_bcat [NQKV];
__device__ float g_QKV  [(size_t)MTOT * NQKV];
__device__ float g_Att  [(size_t)MTOT * DMODEL];
__device__ float g_X1   [(size_t)MTOT * DMODEL];
__device__ float g_Hbuf [(size_t)MTOT * DMODEL];
__device__ float g_Y2   [(size_t)MTOT * DMODEL];

// ---------------- helpers ---------------------------
__device__ __forceinline__ uint32_t smem_u32(const void* p) {
    uint32_t a;
    asm("{ .reg .u64 t; cvta.to.shared.u64 t, %1; cvt.u32.u64 %0, t; }" : "=r"(a) : "l"(p));
    return a;
}
__device__ __forceinline__ float rna_tf32(float x) {
    uint32_t u;
    asm("cvt.rna.tf32.f32 %0, %1;" : "=r"(u) : "f"(x));
    return __uint_as_float(u);
}
__device__ __forceinline__ void cp_async16(uint32_t saddr, const void* g) {
    asm volatile("cp.async.cg.shared.global [%0], [%1], 16;" :: "r"(saddr), "l"(g) : "memory");
}
__device__ __forceinline__ float lds_f32(uint32_t a) {
    float v;
    asm volatile("ld.shared.f32 %0, [%1];" : "=f"(v) : "r"(a));
    return v;
}
// swizzled byte offset of element (row, col) within one [128 x 32] fp32 sub-tile
__device__ __forceinline__ uint32_t swaddr(int row, int col) {
    uint32_t off = (uint32_t)(row * 128 + col * 4);
    return off ^ (((uint32_t)row & 7u) << 4);
}
// D += A*B for m16n8k8 tf32 (operands pre-rounded to tf32-representable fp32)
__device__ __forceinline__ void mma8(float* d, const float* a, const float* b) {
    asm volatile(
        "mma.sync.aligned.m16n8k8.row.col.f32.tf32.tf32.f32 "
        "{%0,%1,%2,%3}, {%4,%5,%6,%7}, {%8,%9}, {%0,%1,%2,%3};"
        : "+f"(d[0]), "+f"(d[1]), "+f"(d[2]), "+f"(d[3])
        : "r"(__float_as_uint(a[0])), "r"(__float_as_uint(a[1])),
          "r"(__float_as_uint(a[2])), "r"(__float_as_uint(a[3])),
          "r"(__float_as_uint(b[0])), "r"(__float_as_uint(b[1])));
}

// ---------------- GEMM: C[m][n] = sum_k A[m][k]*B[n][k] + bias[n] -----------
__device__ __forceinline__ void load_stage(uint32_t sb, const float* __restrict__ gA,
                                           const float* __restrict__ gB, int s) {
    int tid = threadIdx.x;
    uint32_t base = sb + 1024 + (uint32_t)(s % NST) * STAGE_BYTES;
    const float* ga = gA + (size_t)s * BK;
    const float* gb = gB + (size_t)s * BK;
#pragma unroll
    for (int i = 0; i < 8; i++) {
        int c = tid + i * 256;
        int sub = c >> 10;                // k-block 0/1 (cols 0..31 / 32..63)
        int r = (c >> 3) & 127;
        int c16 = c & 7;
        uint32_t off = (uint32_t)(r * 128 + c16 * 16);
        uint32_t sw = off ^ ((off >> 3) & 0x70);
        cp_async16(base + sub * 16384 + sw, ga + (size_t)r * DMODEL + sub * 32 + c16 * 4);
    }
#pragma unroll
    for (int i = 0; i < 8; i++) {
        int c = tid + i * 256;
        int sub = c >> 10;
        int r = (c >> 3) & 127;
        int c16 = c & 7;
        uint32_t off = (uint32_t)(r * 128 + c16 * 16);
        uint32_t sw = off ^ ((off >> 3) & 0x70);
        cp_async16(base + STAGE_A + sub * 16384 + sw, gb + (size_t)r * DMODEL + sub * 32 + c16 * 4);
    }
}

__global__ void __launch_bounds__(256, 1) gemm_tf32(
    const float* __restrict__ A, const float* __restrict__ B,
    const float* __restrict__ bias, float* __restrict__ C,
    int Ntot, int act)
{
    extern __shared__ __align__(1024) char smem[];
    uint32_t sb = smem_u32(smem);
    const int NT = Ntot / BN;
    int tileM = blockIdx.x / NT;
    int tileN = blockIdx.x % NT;                   // n fastest -> B stays L2-resident
    size_t m0 = (size_t)tileM * BM;
    size_t n0 = (size_t)tileN * BN;
    int tid = threadIdx.x, wid = tid >> 5, lane = tid & 31;
    int wm = wid & 1, wn = wid >> 1;               // 2(M) x 4(N) warp grid, 64x32 warp tile
    int lr = lane >> 2;                            // 0..7
    int lc = lane & 3;                             // 0..3

    const float* gA = A + m0 * DMODEL;
    const float* gB = B + n0 * DMODEL;

    float acc[4][4][4];
#pragma unroll
    for (int i = 0; i < 4; i++)
#pragma unroll
        for (int j = 0; j < 4; j++)
#pragma unroll
            for (int r = 0; r < 4; r++) acc[i][j][r] = 0.f;

    // prologue: NST-1 stages in flight
    for (int s = 0; s < NST - 1; s++) {
        load_stage(sb, gA, gB, s);
        asm volatile("cp.async.commit_group;" ::: "memory");
    }

    for (int kt = 0; kt < KT; kt++) {
        asm volatile("cp.async.wait_group %0;" :: "n"(NST - 2) : "memory");
        __syncthreads();   // stage kt readable by all; all warps done with stage (kt-1)%NST

        // prefetch next stage FIRST so the copy overlaps this iteration's compute.
        // Buffer (kt+NST-1)%NST == (kt-1)%NST was last read in iteration kt-1 (proven
        // finished by the barrier above), so overwriting it now is safe.
        if (kt + NST - 1 < KT) load_stage(sb, gA, gB, kt + NST - 1);
        asm volatile("cp.async.commit_group;" ::: "memory");  // empty group in tail keeps counts uniform

        uint32_t sA = sb + 1024 + (uint32_t)(kt % NST) * STAGE_BYTES;
        uint32_t sB = sA + STAGE_A;
#pragma unroll
        for (int ks = 0; ks < 8; ks++) {
            uint32_t bA = sA + (ks >> 2) * 16384;
            uint32_t bB = sB + (ks >> 2) * 16384;
            const int k0 = (ks & 3) * 8;
            float a[4][4];
#pragma unroll
            for (int mf = 0; mf < 4; mf++) {
                int r0 = wm * 64 + mf * 16 + lr;
                a[mf][0] = lds_f32(bA + swaddr(r0,     k0 + lc));
                a[mf][1] = lds_f32(bA + swaddr(r0 + 8, k0 + lc));
                a[mf][2] = lds_f32(bA + swaddr(r0,     k0 + lc + 4));
                a[mf][3] = lds_f32(bA + swaddr(r0 + 8, k0 + lc + 4));
            }
            float b[4][2];
#pragma unroll
            for (int nf = 0; nf < 4; nf++) {
                int n = wn * 32 + nf * 8 + lr;
                b[nf][0] = lds_f32(bB + swaddr(n, k0 + lc));
                b[nf][1] = lds_f32(bB + swaddr(n, k0 + lc + 4));
            }
#pragma unroll
            for (int mf = 0; mf < 4; mf++)
#pragma unroll
                for (int nf = 0; nf < 4; nf++)
                    mma8(acc[mf][nf], a[mf], b[nf]);
        }
    }

    // ---- epilogue: bias (+ exact GELU + tf32 round), vectorized stores ----
#pragma unroll
    for (int mf = 0; mf < 4; mf++) {
        size_t row0 = m0 + (size_t)(wm * 64 + mf * 16 + lr);
#pragma unroll
        for (int nf = 0; nf < 4; nf++) {
            size_t col = n0 + (size_t)(wn * 32 + nf * 8 + 2 * lc);
            float b0 = __ldg(bias + col), b1 = __ldg(bias + col + 1);
            float v[4] = { acc[mf][nf][0] + b0, acc[mf][nf][1] + b1,
                           acc[mf][nf][2] + b0, acc[mf][nf][3] + b1 };
            if (act) {
#pragma unroll
                for (int r = 0; r < 4; r++) {
                    float x = v[r];
                    x = 0.5f * x * (1.0f + erff(x * 0.70710678118654752f));
                    v[r] = rna_tf32(x);
                }
            }
            *(float2*)(C + row0 * (size_t)Ntot + col)       = make_float2(v[0], v[1]);
            *(float2*)(C + (row0 + 8) * (size_t)Ntot + col) = make_float2(v[2], v[3]);
        }
    }
}

// ---------------- attention (per-token head x head softmax) ----------------
__global__ void __launch_bounds__(128) attn_kernel(const float* __restrict__ QKV,
                                                   float* __restrict__ Y)
{
    __shared__ float sq[2048], sk[2048], sv[2048];
    __shared__ float att[16][17];
    int m = blockIdx.x;
    int tid = threadIdx.x;
    const float4* src = (const float4*)(QKV + (size_t)m * NQKV);
#pragma unroll
    for (int i = 0; i < 4; i++) ((float4*)sq)[tid + i * 128] = src[tid + i * 128];
#pragma unroll
    for (int i = 0; i < 4; i++) ((float4*)sk)[tid + i * 128] = src[512 + tid + i * 128];
#pragma unroll
    for (int i = 0; i < 4; i++) ((float4*)sv)[tid + i * 128] = src[1024 + tid + i * 128];
    __syncthreads();

    int lane = tid & 31;
#pragma unroll
    for (int pp = 0; pp < 2; pp++) {
        int p = tid + pp * 128;
        int h = p >> 4, t = p & 15;
        float s = 0.f;
#pragma unroll 8
        for (int i = 0; i < 128; i++) {
            int idx = (lane + i) & 127;          // bank-conflict-free rotation
            s += sq[h * 128 + idx] * sk[t * 128 + idx];
        }
        att[h][t] = s * 0.08838834764831843f;    // 1/sqrt(128)
    }
    __syncthreads();

    if (tid < 16) {
        float mx = -1e30f;
#pragma unroll
        for (int t = 0; t < 16; t++) mx = fmaxf(mx, att[tid][t]);
        float s = 0.f;
#pragma unroll
        for (int t = 0; t < 16; t++) { float e = expf(att[tid][t] - mx); att[tid][t] = e; s += e; }
        float inv = 1.f / s;
#pragma unroll
        for (int t = 0; t < 16; t++) att[tid][t] *= inv;
    }
    __syncthreads();

    int d = tid;  // 0..127
    float* yrow = Y + (size_t)m * DMODEL;
#pragma unroll
    for (int h = 0; h < 16; h++) {
        float s = 0.f;
#pragma unroll
        for (int t = 0; t < 16; t++) s += att[h][t] * sv[t * 128 + d];
        yrow[h * 128 + d] = s;
    }
}

// ---------------- layer norm (a [+ b] -> LN -> optional tf32 round) --------
__global__ void __launch_bounds__(256) ln_kernel(
    const float* __restrict__ a, const float* __restrict__ b,
    const float* __restrict__ g, const float* __restrict__ beta,
    float* __restrict__ out, int doRound)
{
    __shared__ float red[16];
    int m = blockIdx.x, tid = threadIdx.x;
    int wid = tid >> 5, lane = tid & 31;
    const float4* pa = (const float4*)(a + (size_t)m * DMODEL);
    float4 v0 = pa[tid], v1 = pa[tid + 256];
    if (b) {
        const float4* pb = (const float4*)(b + (size_t)m * DMODEL);
        float4 w0 = pb[tid], w1 = pb[tid + 256];
        v0.x += w0.x; v0.y += w0.y; v0.z += w0.z; v0.w += w0.w;
        v1.x += w1.x; v1.y += w1.y; v1.z += w1.z; v1.w += w1.w;
    }
    float x[8] = {v0.x, v0.y, v0.z, v0.w, v1.x, v1.y, v1.z, v1.w};
    float s = 0.f, s2 = 0.f;
#pragma unroll
    for (int i = 0; i < 8; i++) { s += x[i]; s2 += x[i] * x[i]; }
#pragma unroll
    for (int o = 16; o; o >>= 1) {
        s += __shfl_xor_sync(0xffffffffu, s, o);
        s2 += __shfl_xor_sync(0xffffffffu, s2, o);
    }
    if (lane == 0) { red[wid] = s; red[8 + wid] = s2; }
    __syncthreads();
    if (tid == 0) {
        float ts = 0.f, t2 = 0.f;
#pragma unroll
        for (int i = 0; i < 8; i++) { ts += red[i]; t2 += red[8 + i]; }
        float mean = ts * (1.f / DMODEL);
        float var = t2 * (1.f / DMODEL) - mean * mean;
        red[0] = mean;
        red[1] = rsqrtf(var + 1e-5f);
    }
    __syncthreads();
    float mean = red[0], inv = red[1];

    const float4* pg = (const float4*)g;
    const float4* pbt = (const float4*)beta;
    float4* po = (float4*)(out + (size_t)m * DMODEL);
#pragma unroll
    for (int half = 0; half < 2; half++) {
        int vi = tid + half * 256;
        float4 gg = pg[vi], bb = pbt[vi];
        float4 y;
        y.x = (x[half * 4 + 0] - mean) * inv * gg.x + bb.x;
        y.y = (x[half * 4 + 1] - mean) * inv * gg.y + bb.y;
        y.z = (x[half * 4 + 2] - mean) * inv * gg.z + bb.z;
        y.w = (x[half * 4 + 3] - mean) * inv * gg.w + bb.w;
        if (doRound) {
            y.x = rna_tf32(y.x); y.y = rna_tf32(y.y);
            y.z = rna_tf32(y.z); y.w = rna_tf32(y.w);
        }
        po[vi] = y;
    }
}

// ---------------- prep kernels (fused) ----------------------
// One kernel transposes + tf32-rounds all 5 weight matrices (z selects matrix).
__global__ void transpose_all(const float* __restrict__ Wq, const float* __restrict__ Wk,
                              const float* __restrict__ Wv, const float* __restrict__ W1,
                              const float* __restrict__ W2,
                              float* __restrict__ WTqkv, float* __restrict__ WT1,
                              float* __restrict__ WT2)
{
    __shared__ float t[32][33];
    const float* in;
    float* out;
    switch (blockIdx.z) {
        case 0: in = Wq; out = WTqkv; break;
        case 1: in = Wk; out = WTqkv + (size_t)DMODEL * DMODEL; break;
        case 2: in = Wv; out = WTqkv + (size_t)2 * DMODEL * DMODEL; break;
        case 3: in = W1; out = WT1; break;
        default: in = W2; out = WT2; break;
    }
    int bx = blockIdx.x * 32, by = blockIdx.y * 32;
    int tx = threadIdx.x, ty = threadIdx.y;
    for (int j = ty; j < 32; j += 8)
        t[j][tx] = in[(size_t)(by + j) * DMODEL + bx + tx];
    __syncthreads();
    for (int j = ty; j < 32; j += 8)
        out[(size_t)(bx + j) * DMODEL + by + tx] = rna_tf32(t[tx][j]);
}

// Round X to tf32 grid + concat qkv bias, one launch.
__global__ void round_prep(const float* __restrict__ X, float* __restrict__ Xr,
                           const float* __restrict__ bq, const float* __restrict__ bk,
                           const float* __restrict__ bv, float* __restrict__ bcat)
{
    int i = blockIdx.x * blockDim.x + threadIdx.x;
    if (i < NVECX) {
        float4 v = ((const float4*)X)[i];
        v.x = rna_tf32(v.x); v.y = rna_tf32(v.y);
        v.z = rna_tf32(v.z); v.w = rna_tf32(v.w);
        ((float4*)Xr)[i] = v;
    } else {
        int e = i - NVECX;
        if (e < NQKV)
            bcat[e] = (e < DMODEL) ? bq[e]
                    : (e < 2 * DMODEL ? bk[e - DMODEL] : bv[e - 2 * DMODEL]);
    }
}

// ---------------- launch -----------------------------
extern "C" void kernel_launch(void* const* d_in, const int* in_sizes, int n_in,
                              void* d_out, int out_size)
{
    const float* X    = (const float*)d_in[0];
    const float* Wq   = (const float*)d_in[1];
    const float* bq   = (const float*)d_in[2];
    const float* Wk   = (const float*)d_in[3];
    const float* bk   = (const float*)d_in[4];
    const float* Wv   = (const float*)d_in[5];
    const float* bv   = (const float*)d_in[6];
    const float* g1   = (const float*)d_in[7];
    const float* bt1  = (const float*)d_in[8];
    const float* W1   = (const float*)d_in[9];
    const float* b1   = (const float*)d_in[10];
    const float* W2   = (const float*)d_in[11];
    const float* b2   = (const float*)d_in[12];
    const float* g2   = (const float*)d_in[13];
    const float* bt2  = (const float*)d_in[14];
    float* out = (float*)d_out;

    float *pXr, *pWTqkv, *pWT1, *pWT2, *pbcat, *pQKV, *pAtt, *pX1, *pH, *pY2;
    cudaGetSymbolAddress((void**)&pXr,    g_Xr);
    cudaGetSymbolAddress((void**)&pWTqkv, g_WTqkv);
    cudaGetSymbolAddress((void**)&pWT1,   g_WT1);
    cudaGetSymbolAddress((void**)&pWT2,   g_WT2);
    cudaGetSymbolAddress((void**)&pbcat,  g_bcat);
    cudaGetSymbolAddress((void**)&pQKV,   g_QKV);
    cudaGetSymbolAddress((void**)&pAtt,   g_Att);
    cudaGetSymbolAddress((void**)&pX1,    g_X1);
    cudaGetSymbolAddress((void**)&pH,     g_Hbuf);
    cudaGetSymbolAddress((void**)&pY2,    g_Y2);

    cudaFuncSetAttribute(gemm_tf32, cudaFuncAttributeMaxDynamicSharedMemorySize, SMEM_GEMM);

    // launch 1: all weight transposes (+tf32 round)
    dim3 tb(32, 8), tg(DMODEL / 32, DMODEL / 32, 5);
    transpose_all<<<tg, tb>>>(Wq, Wk, Wv, W1, W2, pWTqkv, pWT1, pWT2);
    // launch 2: round X + concat qkv bias
    round_prep<<<(NVECX + NQKV + 255) / 256, 256>>>(X, pXr, bq, bk, bv, pbcat);

    // launch 3: fused QKV projection [16384 x 2048] @ [2048 x 6144]
    gemm_tf32<<<(MTOT / BM) * (NQKV / BN), 256, SMEM_GEMM>>>(pXr, pWTqkv, pbcat, pQKV, NQKV, 0);
    // launch 4: per-token head-softmax attention
    attn_kernel<<<MTOT, 128>>>(pQKV, pAtt);
    // launch 5: residual + LN1 (tf32-rounded: feeds next GEMM)
    ln_kernel<<<MTOT, 256>>>(X, pAtt, g1, bt1, pX1, 1);
    // launch 6 (ncu -s 5 -c 1 captures this): FFN1 with exact GELU
    gemm_tf32<<<(MTOT / BM) * (DMODEL / BN), 256, SMEM_GEMM>>>(pX1, pWT1, b1, pH, DMODEL, 1);
    // launch 7: FFN2
    gemm_tf32<<<(MTOT / BM) * (DMODEL / BN), 256, SMEM_GEMM>>>(pH, pWT2, b2, pY2, DMODEL, 0);
    // launch 8: residual + LN2 -> output
    ln_kernel<<<MTOT, 256>>>(pX1, pY2, g2, bt2, out, 0);
}

// round 5
// speedup vs baseline: 2.0588x; 2.0339x over previous
#include <cuda_runtime.h>
#include <cuda_fp16.h>
#include <cstdint>

// ---------------- problem constants ----------------
#define DMODEL 2048
#define MTOT   16384          // B*S
#define NQKV   6144           // 3*DMODEL
#define NVECX  (MTOT * DMODEL / 4)

// ---------------- GEMM tiling ----------------------
#define BM 128
#define BN 256
#define BK 64
#define NST 4
#define KT (DMODEL / BK)        // 32
#define STAGE_A (BM * 128)      // 16 KB  (64 halves = 128 B per row)
#define STAGE_B (BN * 128)      // 32 KB
#define STAGE_BYTES (STAGE_A + STAGE_B)          // 48 KB
#define SMEM_GEMM (1024 + NST * STAGE_BYTES)     // 197632 B

// ---------------- device scratch --------------------
__device__ __half g_Xh   [(size_t)MTOT * DMODEL];
__device__ __half g_WTqkv[(size_t)NQKV * DMODEL];
__device__ __half g_WT1  [(size_t)DMODEL * DMODEL];
__device__ __half g_WT2  [(size_t)DMODEL * DMODEL];
__device__ float  g_bcat [NQKV];
__device__ float  g_QKV  [(size_t)MTOT * NQKV];
__device__ float  g_Att  [(size_t)MTOT * DMODEL];
__device__ float  g_X1   [(size_t)MTOT * DMODEL];
__device__ __half g_X1h  [(size_t)MTOT * DMODEL];
__device__ __half g_Hh   [(size_t)MTOT * DMODEL];
__device__ float  g_Y2   [(size_t)MTOT * DMODEL];

// ---------------- helpers ---------------------------
__device__ __forceinline__ uint32_t smem_u32(const void* p) {
    uint32_t a;
    asm("{ .reg .u64 t; cvta.to.shared.u64 t, %1; cvt.u32.u64 %0, t; }" : "=r"(a) : "l"(p));
    return a;
}
__device__ __forceinline__ void cp_async16(uint32_t saddr, const void* g) {
    asm volatile("cp.async.cg.shared.global [%0], [%1], 16;" :: "r"(saddr), "l"(g) : "memory");
}
// swizzled byte offset of (row, k-half) in a tile with 128B rows (64 halves)
__device__ __forceinline__ uint32_t swoff(int row, int kh) {
    uint32_t off = (uint32_t)(row * 128 + kh * 2);
    return off ^ ((off >> 3) & 0x70);
}
__device__ __forceinline__ void ldmx4(uint32_t* r, uint32_t addr) {
    asm volatile("ldmatrix.sync.aligned.m8n8.x4.shared.b16 {%0,%1,%2,%3}, [%4];"
                 : "=r"(r[0]), "=r"(r[1]), "=r"(r[2]), "=r"(r[3]) : "r"(addr));
}
__device__ __forceinline__ void mma16(float* d, const uint32_t* a, const uint32_t* b) {
    asm volatile(
        "mma.sync.aligned.m16n8k16.row.col.f32.f16.f16.f32 "
        "{%0,%1,%2,%3}, {%4,%5,%6,%7}, {%8,%9}, {%0,%1,%2,%3};"
        : "+f"(d[0]), "+f"(d[1]), "+f"(d[2]), "+f"(d[3])
        : "r"(a[0]), "r"(a[1]), "r"(a[2]), "r"(a[3]), "r"(b[0]), "r"(b[1]));
}

// ---------------- GEMM: C[m][n] = sum_k A[m][k]*B[n][k] + bias[n] -----------
__device__ __forceinline__ void load_stage(uint32_t sb, const __half* __restrict__ gA,
                                           const __half* __restrict__ gB, int s) {
    int tid = threadIdx.x;
    uint32_t base = sb + 1024 + (uint32_t)(s % NST) * STAGE_BYTES;
    const __half* ga = gA + (size_t)s * BK;
    const __half* gb = gB + (size_t)s * BK;
#pragma unroll
    for (int i = 0; i < 4; i++) {              // A: 128 rows x 8 chunks = 1024
        int c = tid + i * 256;
        int r = c >> 3, c16 = c & 7;
        uint32_t off = (uint32_t)(r * 128 + c16 * 16);
        uint32_t sw = off ^ ((off >> 3) & 0x70);
        cp_async16(base + sw, ga + (size_t)r * DMODEL + c16 * 8);
    }
#pragma unroll
    for (int i = 0; i < 8; i++) {              // B: 256 rows x 8 chunks = 2048
        int c = tid + i * 256;
        int r = c >> 3, c16 = c & 7;
        uint32_t off = (uint32_t)(r * 128 + c16 * 16);
        uint32_t sw = off ^ ((off >> 3) & 0x70);
        cp_async16(base + STAGE_A + sw, gb + (size_t)r * DMODEL + c16 * 8);
    }
}

__global__ void __launch_bounds__(256, 1) gemm_f16(
    const __half* __restrict__ A, const __half* __restrict__ B,
    const float* __restrict__ bias, void* __restrict__ Cout,
    int Ntot, int act, int outHalf)
{
    extern __shared__ __align__(1024) char smem[];
    uint32_t sb = smem_u32(smem);
    const int NT = Ntot / BN;
    int tileM = blockIdx.x / NT;
    int tileN = blockIdx.x % NT;               // n fastest -> B stays L2-resident
    size_t m0 = (size_t)tileM * BM;
    size_t n0 = (size_t)tileN * BN;
    int tid = threadIdx.x, wid = tid >> 5, lane = tid & 31;
    int wm = wid & 1, wn = wid >> 1;           // 2(M) x 4(N) warp grid, 64x64 warp tile

    const __half* gA = A + m0 * DMODEL;
    const __half* gB = B + n0 * DMODEL;

    float acc[4][8][4];
#pragma unroll
    for (int i = 0; i < 4; i++)
#pragma unroll
        for (int j = 0; j < 8; j++)
#pragma unroll
            for (int r = 0; r < 4; r++) acc[i][j][r] = 0.f;

    for (int s = 0; s < NST - 1; s++) {
        load_stage(sb, gA, gB, s);
        asm volatile("cp.async.commit_group;" ::: "memory");
    }

    // ldmatrix per-lane sub-addresses
    int aRow = lane & 15;                      // row within 16
    int aKh  = 8 * (lane >> 4);                // 0 | 8
    int bRow = (lane & 7) + 8 * ((lane >> 4) & 1);
    int bKh  = 8 * ((lane >> 3) & 1);

    for (int kt = 0; kt < KT; kt++) {
        asm volatile("cp.async.wait_group %0;" :: "n"(NST - 2) : "memory");
        __syncthreads();
        if (kt + NST - 1 < KT) load_stage(sb, gA, gB, kt + NST - 1);
        asm volatile("cp.async.commit_group;" ::: "memory");  // empty group in tail keeps counts uniform

        uint32_t sA = sb + 1024 + (uint32_t)(kt % NST) * STAGE_BYTES;
        uint32_t sB = sA + STAGE_A;
#pragma unroll
        for (int ks = 0; ks < 4; ks++) {
            const int k0 = ks * 16;
            uint32_t a[4][4], b[4][4];
#pragma unroll
            for (int mf = 0; mf < 4; mf++)
                ldmx4(a[mf], sA + swoff(wm * 64 + mf * 16 + aRow, k0 + aKh));
#pragma unroll
            for (int nf2 = 0; nf2 < 4; nf2++)
                ldmx4(b[nf2], sB + swoff(wn * 64 + nf2 * 16 + bRow, k0 + bKh));
#pragma unroll
            for (int mf = 0; mf < 4; mf++)
#pragma unroll
                for (int nf = 0; nf < 8; nf++)
                    mma16(acc[mf][nf], a[mf], &b[nf >> 1][(nf & 1) * 2]);
        }
    }

    // ---- epilogue: bias (+ exact GELU), fp32 or fp16 stores ----
    int lr = lane >> 2, lc = lane & 3;
    float* Cf = (float*)Cout;
    __half* Ch = (__half*)Cout;
#pragma unroll
    for (int mf = 0; mf < 4; mf++) {
        size_t row0 = m0 + (size_t)(wm * 64 + mf * 16 + lr);
#pragma unroll
        for (int nf = 0; nf < 8; nf++) {
            size_t col = n0 + (size_t)(wn * 64 + nf * 8 + 2 * lc);
            float b0 = __ldg(bias + col), b1 = __ldg(bias + col + 1);
            float v[4] = { acc[mf][nf][0] + b0, acc[mf][nf][1] + b1,
                           acc[mf][nf][2] + b0, acc[mf][nf][3] + b1 };
            if (act) {
#pragma unroll
                for (int r = 0; r < 4; r++)
                    v[r] = 0.5f * v[r] * (1.0f + erff(v[r] * 0.70710678118654752f));
            }
            if (outHalf) {
                *(__half2*)(Ch + row0 * (size_t)Ntot + col)       = __floats2half2_rn(v[0], v[1]);
                *(__half2*)(Ch + (row0 + 8) * (size_t)Ntot + col) = __floats2half2_rn(v[2], v[3]);
            } else {
                *(float2*)(Cf + row0 * (size_t)Ntot + col)       = make_float2(v[0], v[1]);
                *(float2*)(Cf + (row0 + 8) * (size_t)Ntot + col) = make_float2(v[2], v[3]);
            }
        }
    }
}

// ---------------- attention (per-token head x head softmax) ----------------
__global__ void __launch_bounds__(128) attn_kernel(const float* __restrict__ QKV,
                                                   float* __restrict__ Y)
{
    __shared__ float sq[2048], sk[2048], sv[2048];
    __shared__ float att[16][17];
    int m = blockIdx.x;
    int tid = threadIdx.x;
    const float4* src = (const float4*)(QKV + (size_t)m * NQKV);
#pragma unroll
    for (int i = 0; i < 4; i++) ((float4*)sq)[tid + i * 128] = src[tid + i * 128];
#pragma unroll
    for (int i = 0; i < 4; i++) ((float4*)sk)[tid + i * 128] = src[512 + tid + i * 128];
#pragma unroll
    for (int i = 0; i < 4; i++) ((float4*)sv)[tid + i * 128] = src[1024 + tid + i * 128];
    __syncthreads();

    int lane = tid & 31;
#pragma unroll
    for (int pp = 0; pp < 2; pp++) {
        int p = tid + pp * 128;
        int h = p >> 4, t = p & 15;
        const float4* q4 = (const float4*)(sq + h * 128);
        const float4* k4 = (const float4*)(sk + t * 128);
        float s = 0.f;
#pragma unroll 8
        for (int i = 0; i < 32; i++) {
            int idx = (lane + i) & 31;           // rotation at 16B granularity
            float4 qa = q4[idx], kb = k4[idx];
            s += qa.x * kb.x + qa.y * kb.y + qa.z * kb.z + qa.w * kb.w;
        }
        att[h][t] = s * 0.08838834764831843f;    // 1/sqrt(128)
    }
    __syncthreads();

    if (tid < 16) {
        float mx = -1e30f;
#pragma unroll
        for (int t = 0; t < 16; t++) mx = fmaxf(mx, att[tid][t]);
        float s = 0.f;
#pragma unroll
        for (int t = 0; t < 16; t++) { float e = expf(att[tid][t] - mx); att[tid][t] = e; s += e; }
        float inv = 1.f / s;
#pragma unroll
        for (int t = 0; t < 16; t++) att[tid][t] *= inv;
    }
    __syncthreads();

    int d = tid;  // 0..127
    float* yrow = Y + (size_t)m * DMODEL;
#pragma unroll
    for (int h = 0; h < 16; h++) {
        float s = 0.f;
#pragma unroll
        for (int t = 0; t < 16; t++) s += att[h][t] * sv[t * 128 + d];
        yrow[h * 128 + d] = s;
    }
}

// ---------------- layer norm (a [+ b] -> LN; fp32 out + optional fp16 out) --
__global__ void __launch_bounds__(256) ln_kernel(
    const float* __restrict__ a, const float* __restrict__ b,
    const float* __restrict__ g, const float* __restrict__ beta,
    float* __restrict__ out32, __half* __restrict__ out16)
{
    __shared__ float red[16];
    int m = blockIdx.x, tid = threadIdx.x;
    int wid = tid >> 5, lane = tid & 31;
    const float4* pa = (const float4*)(a + (size_t)m * DMODEL);
    float4 v0 = pa[tid], v1 = pa[tid + 256];
    if (b) {
        const float4* pb = (const float4*)(b + (size_t)m * DMODEL);
        float4 w0 = pb[tid], w1 = pb[tid + 256];
        v0.x += w0.x; v0.y += w0.y; v0.z += w0.z; v0.w += w0.w;
        v1.x += w1.x; v1.y += w1.y; v1.z += w1.z; v1.w += w1.w;
    }
    float x[8] = {v0.x, v0.y, v0.z, v0.w, v1.x, v1.y, v1.z, v1.w};
    float s = 0.f, s2 = 0.f;
#pragma unroll
    for (int i = 0; i < 8; i++) { s += x[i]; s2 += x[i] * x[i]; }
#pragma unroll
    for (int o = 16; o; o >>= 1) {
        s += __shfl_xor_sync(0xffffffffu, s, o);
        s2 += __shfl_xor_sync(0xffffffffu, s2, o);
    }
    if (lane == 0) { red[wid] = s; red[8 + wid] = s2; }
    __syncthreads();
    if (tid == 0) {
        float ts = 0.f, t2 = 0.f;
#pragma unroll
        for (int i = 0; i < 8; i++) { ts += red[i]; t2 += red[8 + i]; }
        float mean = ts * (1.f / DMODEL);
        float var = t2 * (1.f / DMODEL) - mean * mean;
        red[0] = mean;
        red[1] = rsqrtf(var + 1e-5f);
    }
    __syncthreads();
    float mean = red[0], inv = red[1];

    const float4* pg = (const float4*)g;
    const float4* pbt = (const float4*)beta;
    float4* po = (float4*)(out32 + (size_t)m * DMODEL);
    __half2* ph = out16 ? (__half2*)(out16 + (size_t)m * DMODEL) : nullptr;
#pragma unroll
    for (int half_ = 0; half_ < 2; half_++) {
        int vi = tid + half_ * 256;
        float4 gg = pg[vi], bb = pbt[vi];
        float4 y;
        y.x = (x[half_ * 4 + 0] - mean) * inv * gg.x + bb.x;
        y.y = (x[half_ * 4 + 1] - mean) * inv * gg.y + bb.y;
        y.z = (x[half_ * 4 + 2] - mean) * inv * gg.z + bb.z;
        y.w = (x[half_ * 4 + 3] - mean) * inv * gg.w + bb.w;
        po[vi] = y;
        if (ph) {
            ph[2 * vi]     = __floats2half2_rn(y.x, y.y);
            ph[2 * vi + 1] = __floats2half2_rn(y.z, y.w);
        }
    }
}

// ---------------- prep kernels ----------------------
// Transpose + fp16-convert all 5 weight matrices (z selects matrix).
__global__ void transpose_all(const float* __restrict__ Wq, const float* __restrict__ Wk,
                              const float* __restrict__ Wv, const float* __restrict__ W1,
                              const float* __restrict__ W2,
                              __half* __restrict__ WTqkv, __half* __restrict__ WT1,
                              __half* __restrict__ WT2)
{
    __shared__ float t[32][33];
    const float* in;
    __half* out;
    switch (blockIdx.z) {
        case 0: in = Wq; out = WTqkv; break;
        case 1: in = Wk; out = WTqkv + (size_t)DMODEL * DMODEL; break;
        case 2: in = Wv; out = WTqkv + (size_t)2 * DMODEL * DMODEL; break;
        case 3: in = W1; out = WT1; break;
        default: in = W2; out = WT2; break;
    }
    int bx = blockIdx.x * 32, by = blockIdx.y * 32;
    int tx = threadIdx.x, ty = threadIdx.y;
    for (int j = ty; j < 32; j += 8)
        t[j][tx] = in[(size_t)(by + j) * DMODEL + bx + tx];
    __syncthreads();
    for (int j = ty; j < 32; j += 8)
        out[(size_t)(bx + j) * DMODEL + by + tx] = __float2half_rn(t[tx][j]);
}

// X -> fp16 + concat qkv bias, one launch.
__global__ void round_prep(const float* __restrict__ X, __half* __restrict__ Xh,
                           const float* __restrict__ bq, const float* __restrict__ bk,
                           const float* __restrict__ bv, float* __restrict__ bcat)
{
    int i = blockIdx.x * blockDim.x + threadIdx.x;
    if (i < NVECX) {
        float4 v = ((const float4*)X)[i];
        __half2* ph = (__half2*)Xh;
        ph[2 * i]     = __floats2half2_rn(v.x, v.y);
        ph[2 * i + 1] = __floats2half2_rn(v.z, v.w);
    } else {
        int e = i - NVECX;
        if (e < NQKV)
            bcat[e] = (e < DMODEL) ? bq[e]
                    : (e < 2 * DMODEL ? bk[e - DMODEL] : bv[e - 2 * DMODEL]);
    }
}

// ---------------- launch -----------------------------
extern "C" void kernel_launch(void* const* d_in, const int* in_sizes, int n_in,
                              void* d_out, int out_size)
{
    const float* X    = (const float*)d_in[0];
    const float* Wq   = (const float*)d_in[1];
    const float* bq   = (const float*)d_in[2];
    const float* Wk   = (const float*)d_in[3];
    const float* bk   = (const float*)d_in[4];
    const float* Wv   = (const float*)d_in[5];
    const float* bv   = (const float*)d_in[6];
    const float* g1   = (const float*)d_in[7];
    const float* bt1  = (const float*)d_in[8];
    const float* W1   = (const float*)d_in[9];
    const float* b1   = (const float*)d_in[10];
    const float* W2   = (const float*)d_in[11];
    const float* b2   = (const float*)d_in[12];
    const float* g2   = (const float*)d_in[13];
    const float* bt2  = (const float*)d_in[14];
    float* out = (float*)d_out;

    __half *pXh, *pWTqkv, *pWT1, *pWT2, *pX1h, *pHh;
    float *pbcat, *pQKV, *pAtt, *pX1, *pY2;
    cudaGetSymbolAddress((void**)&pXh,    g_Xh);
    cudaGetSymbolAddress((void**)&pWTqkv, g_WTqkv);
    cudaGetSymbolAddress((void**)&pWT1,   g_WT1);
    cudaGetSymbolAddress((void**)&pWT2,   g_WT2);
    cudaGetSymbolAddress((void**)&pbcat,  g_bcat);
    cudaGetSymbolAddress((void**)&pQKV,   g_QKV);
    cudaGetSymbolAddress((void**)&pAtt,   g_Att);
    cudaGetSymbolAddress((void**)&pX1,    g_X1);
    cudaGetSymbolAddress((void**)&pX1h,   g_X1h);
    cudaGetSymbolAddress((void**)&pHh,    g_Hh);
    cudaGetSymbolAddress((void**)&pY2,    g_Y2);

    cudaFuncSetAttribute(gemm_f16, cudaFuncAttributeMaxDynamicSharedMemorySize, SMEM_GEMM);

    // launch 1: all weight transposes (+fp16 convert)
    dim3 tb(32, 8), tg(DMODEL / 32, DMODEL / 32, 5);
    transpose_all<<<tg, tb>>>(Wq, Wk, Wv, W1, W2, pWTqkv, pWT1, pWT2);
    // launch 2: X -> fp16 + concat qkv bias
    round_prep<<<(NVECX + NQKV + 255) / 256, 256>>>(X, pXh, bq, bk, bv, pbcat);

    // launch 3: fused QKV projection [16384 x 2048] @ [2048 x 6144] -> fp32
    gemm_f16<<<(MTOT / BM) * (NQKV / BN), 256, SMEM_GEMM>>>(pXh, pWTqkv, pbcat, pQKV, NQKV, 0, 0);
    // launch 4: per-token head-softmax attention
    attn_kernel<<<MTOT, 128>>>(pQKV, pAtt);
    // launch 5: residual + LN1 -> fp32 (residual) + fp16 (next GEMM A)
    ln_kernel<<<MTOT, 256>>>(X, pAtt, g1, bt1, pX1, pX1h);
    // launch 6: FFN1 + exact GELU -> fp16 (next GEMM A)
    gemm_f16<<<(MTOT / BM) * (DMODEL / BN), 256, SMEM_GEMM>>>(pX1h, pWT1, b1, pHh, DMODEL, 1, 1);
    // launch 7: FFN2 -> fp32
    gemm_f16<<<(MTOT / BM) * (DMODEL / BN), 256, SMEM_GEMM>>>(pHh, pWT2, b2, pY2, DMODEL, 0, 0);
    // launch 8: residual + LN2 -> output
    ln_kernel<<<MTOT, 256>>>(pX1, pY2, g2, bt2, out, nullptr);
}

// round 6
// speedup vs baseline: 2.1403x; 1.0396x over previous
#include <cuda_runtime.h>
#include <cuda_fp16.h>
#include <cstdint>

// ---------------- problem constants ----------------
#define DMODEL 2048
#define MTOT   16384          // B*S
#define NQKV   6144           // 3*DMODEL
#define NVECX  (MTOT * DMODEL / 4)

// ---------------- GEMM tiling ----------------------
#define BM 128
#define BN 256
#define BK 64
#define NST 4
#define KT (DMODEL / BK)        // 32
#define STAGE_A (BM * 128)      // 16 KB  (64 halves = 128 B per row)
#define STAGE_B (BN * 128)      // 32 KB
#define STAGE_BYTES (STAGE_A + STAGE_B)          // 48 KB
#define SMEM_GEMM (1024 + NST * STAGE_BYTES)     // 197632 B

// ---------------- device scratch --------------------
__device__ __half g_Xh   [(size_t)MTOT * DMODEL];
__device__ __half g_WTqkv[(size_t)NQKV * DMODEL];
__device__ __half g_WT1  [(size_t)DMODEL * DMODEL];
__device__ __half g_WT2  [(size_t)DMODEL * DMODEL];
__device__ float  g_bcat [NQKV];
__device__ __half g_QKVh [(size_t)MTOT * NQKV];
__device__ float  g_X1   [(size_t)MTOT * DMODEL];
__device__ __half g_X1h  [(size_t)MTOT * DMODEL];
__device__ __half g_Hh   [(size_t)MTOT * DMODEL];
__device__ float  g_Y2   [(size_t)MTOT * DMODEL];

// ---------------- helpers ---------------------------
__device__ __forceinline__ uint32_t smem_u32(const void* p) {
    uint32_t a;
    asm("{ .reg .u64 t; cvta.to.shared.u64 t, %1; cvt.u32.u64 %0, t; }" : "=r"(a) : "l"(p));
    return a;
}
__device__ __forceinline__ void cp_async16(uint32_t saddr, const void* g) {
    asm volatile("cp.async.cg.shared.global [%0], [%1], 16;" :: "r"(saddr), "l"(g) : "memory");
}
// swizzled byte offset of (row, k-half) in a tile with 128B rows (64 halves)
__device__ __forceinline__ uint32_t swoff(int row, int kh) {
    uint32_t off = (uint32_t)(row * 128 + kh * 2);
    return off ^ ((off >> 3) & 0x70);
}
__device__ __forceinline__ void ldmx4(uint32_t* r, uint32_t addr) {
    asm volatile("ldmatrix.sync.aligned.m8n8.x4.shared.b16 {%0,%1,%2,%3}, [%4];"
                 : "=r"(r[0]), "=r"(r[1]), "=r"(r[2]), "=r"(r[3]) : "r"(addr));
}
__device__ __forceinline__ void mma16(float* d, const uint32_t* a, const uint32_t* b) {
    asm volatile(
        "mma.sync.aligned.m16n8k16.row.col.f32.f16.f16.f32 "
        "{%0,%1,%2,%3}, {%4,%5,%6,%7}, {%8,%9}, {%0,%1,%2,%3};"
        : "+f"(d[0]), "+f"(d[1]), "+f"(d[2]), "+f"(d[3])
        : "r"(a[0]), "r"(a[1]), "r"(a[2]), "r"(a[3]), "r"(b[0]), "r"(b[1]));
}
__device__ __forceinline__ float doth8(uint4 a, uint4 b) {
    const __half2* pa = (const __half2*)&a;
    const __half2* pb = (const __half2*)&b;
    float s = 0.f;
#pragma unroll
    for (int j = 0; j < 4; j++) {
        float2 fa = __half22float2(pa[j]);
        float2 fb = __half22float2(pb[j]);
        s += fa.x * fb.x + fa.y * fb.y;
    }
    return s;
}

// ---------------- GEMM: C[m][n] = sum_k A[m][k]*B[n][k] + bias[n] -----------
__device__ __forceinline__ void load_stage(uint32_t sb, const __half* __restrict__ gA,
                                           const __half* __restrict__ gB, int s) {
    int tid = threadIdx.x;
    uint32_t base = sb + 1024 + (uint32_t)(s % NST) * STAGE_BYTES;
    const __half* ga = gA + (size_t)s * BK;
    const __half* gb = gB + (size_t)s * BK;
#pragma unroll
    for (int i = 0; i < 4; i++) {              // A: 128 rows x 8 chunks = 1024
        int c = tid + i * 256;
        int r = c >> 3, c16 = c & 7;
        uint32_t off = (uint32_t)(r * 128 + c16 * 16);
        uint32_t sw = off ^ ((off >> 3) & 0x70);
        cp_async16(base + sw, ga + (size_t)r * DMODEL + c16 * 8);
    }
#pragma unroll
    for (int i = 0; i < 8; i++) {              // B: 256 rows x 8 chunks = 2048
        int c = tid + i * 256;
        int r = c >> 3, c16 = c & 7;
        uint32_t off = (uint32_t)(r * 128 + c16 * 16);
        uint32_t sw = off ^ ((off >> 3) & 0x70);
        cp_async16(base + STAGE_A + sw, gb + (size_t)r * DMODEL + c16 * 8);
    }
}

__global__ void __launch_bounds__(256, 1) gemm_f16(
    const __half* __restrict__ A, const __half* __restrict__ B,
    const float* __restrict__ bias, void* __restrict__ Cout,
    int Ntot, int act, int outHalf)
{
    extern __shared__ __align__(1024) char smem[];
    uint32_t sb = smem_u32(smem);
    const int NT = Ntot / BN;
    int tileM = blockIdx.x / NT;
    int tileN = blockIdx.x % NT;               // n fastest -> B stays L2-resident
    size_t m0 = (size_t)tileM * BM;
    size_t n0 = (size_t)tileN * BN;
    int tid = threadIdx.x, wid = tid >> 5, lane = tid & 31;
    int wm = wid & 1, wn = wid >> 1;           // 2(M) x 4(N) warp grid, 64x64 warp tile

    const __half* gA = A + m0 * DMODEL;
    const __half* gB = B + n0 * DMODEL;

    float acc[4][8][4];
#pragma unroll
    for (int i = 0; i < 4; i++)
#pragma unroll
        for (int j = 0; j < 8; j++)
#pragma unroll
            for (int r = 0; r < 4; r++) acc[i][j][r] = 0.f;

    for (int s = 0; s < NST - 1; s++) {
        load_stage(sb, gA, gB, s);
        asm volatile("cp.async.commit_group;" ::: "memory");
    }

    // ldmatrix per-lane sub-addresses
    int aRow = lane & 15;                      // row within 16
    int aKh  = 8 * (lane >> 4);                // 0 | 8
    int bRow = (lane & 7) + 8 * ((lane >> 4) & 1);
    int bKh  = 8 * ((lane >> 3) & 1);

    for (int kt = 0; kt < KT; kt++) {
        asm volatile("cp.async.wait_group %0;" :: "n"(NST - 2) : "memory");
        __syncthreads();
        if (kt + NST - 1 < KT) load_stage(sb, gA, gB, kt + NST - 1);
        asm volatile("cp.async.commit_group;" ::: "memory");  // empty group in tail keeps counts uniform

        uint32_t sA = sb + 1024 + (uint32_t)(kt % NST) * STAGE_BYTES;
        uint32_t sB = sA + STAGE_A;
#pragma unroll
        for (int ks = 0; ks < 4; ks++) {
            const int k0 = ks * 16;
            uint32_t a[4][4], b[4][4];
#pragma unroll
            for (int mf = 0; mf < 4; mf++)
                ldmx4(a[mf], sA + swoff(wm * 64 + mf * 16 + aRow, k0 + aKh));
#pragma unroll
            for (int nf2 = 0; nf2 < 4; nf2++)
                ldmx4(b[nf2], sB + swoff(wn * 64 + nf2 * 16 + bRow, k0 + bKh));
#pragma unroll
            for (int mf = 0; mf < 4; mf++)
#pragma unroll
                for (int nf = 0; nf < 8; nf++)
                    mma16(acc[mf][nf], a[mf], &b[nf >> 1][(nf & 1) * 2]);
        }
    }

    // ---- epilogue: bias (+ exact GELU), fp32 or fp16 stores ----
    int lr = lane >> 2, lc = lane & 3;
    float* Cf = (float*)Cout;
    __half* Ch = (__half*)Cout;
#pragma unroll
    for (int mf = 0; mf < 4; mf++) {
        size_t row0 = m0 + (size_t)(wm * 64 + mf * 16 + lr);
#pragma unroll
        for (int nf = 0; nf < 8; nf++) {
            size_t col = n0 + (size_t)(wn * 64 + nf * 8 + 2 * lc);
            float b0 = __ldg(bias + col), b1 = __ldg(bias + col + 1);
            float v[4] = { acc[mf][nf][0] + b0, acc[mf][nf][1] + b1,
                           acc[mf][nf][2] + b0, acc[mf][nf][3] + b1 };
            if (act) {
#pragma unroll
                for (int r = 0; r < 4; r++)
                    v[r] = 0.5f * v[r] * (1.0f + erff(v[r] * 0.70710678118654752f));
            }
            if (outHalf) {
                *(__half2*)(Ch + row0 * (size_t)Ntot + col)       = __floats2half2_rn(v[0], v[1]);
                *(__half2*)(Ch + (row0 + 8) * (size_t)Ntot + col) = __floats2half2_rn(v[2], v[3]);
            } else {
                *(float2*)(Cf + row0 * (size_t)Ntot + col)       = make_float2(v[0], v[1]);
                *(float2*)(Cf + (row0 + 8) * (size_t)Ntot + col) = make_float2(v[2], v[3]);
            }
        }
    }
}

// ------- attention (head x head softmax) fused with residual + LN1 ---------
// One block = one token. Produces X1 (fp32) and X1h (fp16) directly.
__global__ void __launch_bounds__(128) attn_ln_kernel(
    const __half* __restrict__ QKVh, const float* __restrict__ X,
    const float* __restrict__ g, const float* __restrict__ beta,
    float* __restrict__ X1, __half* __restrict__ X1h)
{
    __shared__ __half sqkv[NQKV];              // 12 KB: q | k | v
    __shared__ float att[16][17];
    __shared__ float red[10];
    int m = blockIdx.x, tid = threadIdx.x;
    int wid = tid >> 5, lane = tid & 31;

    const uint4* src = (const uint4*)(QKVh + (size_t)m * NQKV);
    uint4* dst = (uint4*)sqkv;
#pragma unroll
    for (int i = 0; i < 6; i++) dst[tid + i * 128] = src[tid + i * 128];
    __syncthreads();

    const __half* sq = sqkv;
    const __half* sk = sqkv + 2048;
    const __half* sv = sqkv + 4096;

    // ---- QK^T (16x16 per token), 2 pairs per thread ----
#pragma unroll
    for (int pp = 0; pp < 2; pp++) {
        int p = tid + pp * 128;
        int h = p >> 4, t = p & 15;
        const uint4* q4 = (const uint4*)(sq + h * 128);
        const uint4* k4 = (const uint4*)(sk + t * 128);
        float s = 0.f;
#pragma unroll
        for (int i = 0; i < 16; i++) {
            int idx = (lane + i) & 15;         // rotate to spread banks
            s += doth8(q4[idx], k4[idx]);
        }
        att[h][t] = s * 0.08838834764831843f;  // 1/sqrt(128)
    }
    __syncthreads();

    // ---- softmax over t for each h ----
    if (tid < 16) {
        float mx = -1e30f;
#pragma unroll
        for (int t = 0; t < 16; t++) mx = fmaxf(mx, att[tid][t]);
        float s = 0.f;
#pragma unroll
        for (int t = 0; t < 16; t++) { float e = expf(att[tid][t] - mx); att[tid][t] = e; s += e; }
        float inv = 1.f / s;
#pragma unroll
        for (int t = 0; t < 16; t++) att[tid][t] *= inv;
    }
    __syncthreads();

    // ---- AV with register-cached V, + residual, LN statistics ----
    int d = tid;                               // 0..127
    float v[16];
#pragma unroll
    for (int t = 0; t < 16; t++) v[t] = __half2float(sv[t * 128 + d]);

    float y[16];
    float s = 0.f, s2 = 0.f;
    const float* xrow = X + (size_t)m * DMODEL;
#pragma unroll
    for (int h = 0; h < 16; h++) {
        float acc = 0.f;
#pragma unroll
        for (int t = 0; t < 16; t++) acc += att[h][t] * v[t];   // att: broadcast reads
        float z = xrow[h * 128 + d] + acc;
        y[h] = z; s += z; s2 += z * z;
    }
#pragma unroll
    for (int o = 16; o; o >>= 1) {
        s  += __shfl_xor_sync(0xffffffffu, s, o);
        s2 += __shfl_xor_sync(0xffffffffu, s2, o);
    }
    if (lane == 0) { red[wid] = s; red[4 + wid] = s2; }
    __syncthreads();
    if (tid == 0) {
        float ts = red[0] + red[1] + red[2] + red[3];
        float t2 = red[4] + red[5] + red[6] + red[7];
        float mean = ts * (1.f / DMODEL);
        float var = t2 * (1.f / DMODEL) - mean * mean;
        red[8] = mean;
        red[9] = rsqrtf(var + 1e-5f);
    }
    __syncthreads();
    float mean = red[8], inv = red[9];

    float* o32 = X1 + (size_t)m * DMODEL;
    __half* o16 = X1h + (size_t)m * DMODEL;
#pragma unroll
    for (int h = 0; h < 16; h++) {
        int c = h * 128 + d;
        float o = (y[h] - mean) * inv * __ldg(g + c) + __ldg(beta + c);
        o32[c] = o;
        o16[c] = __float2half_rn(o);
    }
}

// ---------------- layer norm (a + b -> LN -> fp32 out), used for LN2 -------
__global__ void __launch_bounds__(256) ln_kernel(
    const float* __restrict__ a, const float* __restrict__ b,
    const float* __restrict__ g, const float* __restrict__ beta,
    float* __restrict__ out32)
{
    __shared__ float red[18];
    int m = blockIdx.x, tid = threadIdx.x;
    int wid = tid >> 5, lane = tid & 31;
    const float4* pa = (const float4*)(a + (size_t)m * DMODEL);
    const float4* pb = (const float4*)(b + (size_t)m * DMODEL);
    float4 v0 = pa[tid], v1 = pa[tid + 256];
    float4 w0 = pb[tid], w1 = pb[tid + 256];
    v0.x += w0.x; v0.y += w0.y; v0.z += w0.z; v0.w += w0.w;
    v1.x += w1.x; v1.y += w1.y; v1.z += w1.z; v1.w += w1.w;
    float x[8] = {v0.x, v0.y, v0.z, v0.w, v1.x, v1.y, v1.z, v1.w};
    float s = 0.f, s2 = 0.f;
#pragma unroll
    for (int i = 0; i < 8; i++) { s += x[i]; s2 += x[i] * x[i]; }
#pragma unroll
    for (int o = 16; o; o >>= 1) {
        s += __shfl_xor_sync(0xffffffffu, s, o);
        s2 += __shfl_xor_sync(0xffffffffu, s2, o);
    }
    if (lane == 0) { red[wid] = s; red[8 + wid] = s2; }
    __syncthreads();
    if (tid == 0) {
        float ts = 0.f, t2 = 0.f;
#pragma unroll
        for (int i = 0; i < 8; i++) { ts += red[i]; t2 += red[8 + i]; }
        float mean = ts * (1.f / DMODEL);
        float var = t2 * (1.f / DMODEL) - mean * mean;
        red[16] = mean;
        red[17] = rsqrtf(var + 1e-5f);
    }
    __syncthreads();
    float mean = red[16], inv = red[17];

    const float4* pg = (const float4*)g;
    const float4* pbt = (const float4*)beta;
    float4* po = (float4*)(out32 + (size_t)m * DMODEL);
#pragma unroll
    for (int half_ = 0; half_ < 2; half_++) {
        int vi = tid + half_ * 256;
        float4 gg = pg[vi], bb = pbt[vi];
        float4 y;
        y.x = (x[half_ * 4 + 0] - mean) * inv * gg.x + bb.x;
        y.y = (x[half_ * 4 + 1] - mean) * inv * gg.y + bb.y;
        y.z = (x[half_ * 4 + 2] - mean) * inv * gg.z + bb.z;
        y.w = (x[half_ * 4 + 3] - mean) * inv * gg.w + bb.w;
        po[vi] = y;
    }
}

// ---------------- prep kernels ----------------------
__global__ void transpose_all(const float* __restrict__ Wq, const float* __restrict__ Wk,
                              const float* __restrict__ Wv, const float* __restrict__ W1,
                              const float* __restrict__ W2,
                              __half* __restrict__ WTqkv, __half* __restrict__ WT1,
                              __half* __restrict__ WT2)
{
    __shared__ float t[32][33];
    const float* in;
    __half* out;
    switch (blockIdx.z) {
        case 0: in = Wq; out = WTqkv; break;
        case 1: in = Wk; out = WTqkv + (size_t)DMODEL * DMODEL; break;
        case 2: in = Wv; out = WTqkv + (size_t)2 * DMODEL * DMODEL; break;
        case 3: in = W1; out = WT1; break;
        default: in = W2; out = WT2; break;
    }
    int bx = blockIdx.x * 32, by = blockIdx.y * 32;
    int tx = threadIdx.x, ty = threadIdx.y;
    for (int j = ty; j < 32; j += 8)
        t[j][tx] = in[(size_t)(by + j) * DMODEL + bx + tx];
    __syncthreads();
    for (int j = ty; j < 32; j += 8)
        out[(size_t)(bx + j) * DMODEL + by + tx] = __float2half_rn(t[tx][j]);
}

__global__ void round_prep(const float* __restrict__ X, __half* __restrict__ Xh,
                           const float* __restrict__ bq, const float* __restrict__ bk,
                           const float* __restrict__ bv, float* __restrict__ bcat)
{
    int i = blockIdx.x * blockDim.x + threadIdx.x;
    if (i < NVECX) {
        float4 v = ((const float4*)X)[i];
        __half2* ph = (__half2*)Xh;
        ph[2 * i]     = __floats2half2_rn(v.x, v.y);
        ph[2 * i + 1] = __floats2half2_rn(v.z, v.w);
    } else {
        int e = i - NVECX;
        if (e < NQKV)
            bcat[e] = (e < DMODEL) ? bq[e]
                    : (e < 2 * DMODEL ? bk[e - DMODEL] : bv[e - 2 * DMODEL]);
    }
}

// ---------------- launch -----------------------------
extern "C" void kernel_launch(void* const* d_in, const int* in_sizes, int n_in,
                              void* d_out, int out_size)
{
    const float* X    = (const float*)d_in[0];
    const float* Wq   = (const float*)d_in[1];
    const float* bq   = (const float*)d_in[2];
    const float* Wk   = (const float*)d_in[3];
    const float* bk   = (const float*)d_in[4];
    const float* Wv   = (const float*)d_in[5];
    const float* bv   = (const float*)d_in[6];
    const float* g1   = (const float*)d_in[7];
    const float* bt1  = (const float*)d_in[8];
    const float* W1   = (const float*)d_in[9];
    const float* b1   = (const float*)d_in[10];
    const float* W2   = (const float*)d_in[11];
    const float* b2   = (const float*)d_in[12];
    const float* g2   = (const float*)d_in[13];
    const float* bt2  = (const float*)d_in[14];
    float* out = (float*)d_out;

    __half *pXh, *pWTqkv, *pWT1, *pWT2, *pQKVh, *pX1h, *pHh;
    float *pbcat, *pX1, *pY2;
    cudaGetSymbolAddress((void**)&pXh,    g_Xh);
    cudaGetSymbolAddress((void**)&pWTqkv, g_WTqkv);
    cudaGetSymbolAddress((void**)&pWT1,   g_WT1);
    cudaGetSymbolAddress((void**)&pWT2,   g_WT2);
    cudaGetSymbolAddress((void**)&pbcat,  g_bcat);
    cudaGetSymbolAddress((void**)&pQKVh,  g_QKVh);
    cudaGetSymbolAddress((void**)&pX1,    g_X1);
    cudaGetSymbolAddress((void**)&pX1h,   g_X1h);
    cudaGetSymbolAddress((void**)&pHh,    g_Hh);
    cudaGetSymbolAddress((void**)&pY2,    g_Y2);

    cudaFuncSetAttribute(gemm_f16, cudaFuncAttributeMaxDynamicSharedMemorySize, SMEM_GEMM);

    // launch 1: all weight transposes (+fp16 convert)
    dim3 tb(32, 8), tg(DMODEL / 32, DMODEL / 32, 5);
    transpose_all<<<tg, tb>>>(Wq, Wk, Wv, W1, W2, pWTqkv, pWT1, pWT2);
    // launch 2: X -> fp16 + concat qkv bias
    round_prep<<<(NVECX + NQKV + 255) / 256, 256>>>(X, pXh, bq, bk, bv, pbcat);

    // launch 3: fused QKV projection -> fp16 (feeds attention)
    gemm_f16<<<(MTOT / BM) * (NQKV / BN), 256, SMEM_GEMM>>>(pXh, pWTqkv, pbcat, pQKVh, NQKV, 0, 1);
    // launch 4: attention + residual + LN1 (fused) -> X1 fp32, X1h fp16
    attn_ln_kernel<<<MTOT, 128>>>(pQKVh, X, g1, bt1, pX1, pX1h);
    // launch 5: FFN1 + exact GELU -> fp16
    gemm_f16<<<(MTOT / BM) * (DMODEL / BN), 256, SMEM_GEMM>>>(pX1h, pWT1, b1, pHh, DMODEL, 1, 1);
    // launch 6 (ncu lands here): FFN2 -> fp32
    gemm_f16<<<(MTOT / BM) * (DMODEL / BN), 256, SMEM_GEMM>>>(pHh, pWT2, b2, pY2, DMODEL, 0, 0);
    // launch 7: residual + LN2 -> output
    ln_kernel<<<MTOT, 256>>>(pX1, pY2, g2, bt2, out);
}